// round 10
// baseline (speedup 1.0000x reference)
#include <cuda_runtime.h>
#include <cuda_fp16.h>
#include <cstdint>

// ---------------------------------------------------------------------------
// Problem dims
// ---------------------------------------------------------------------------
#define I_DIM 4096   // K
#define O_DIM 4096   // N
#define M_DIM 8192   // B*S
#define R_DIM 4

// GEMM tiling: 256(M) x 128(N) x 64(K) CTA tile, 512 threads = 16 warps
// as 4(m) x 4(n), warp tile 64x32. Cuts L2 traffic 25% vs 128x128 while
// keeping 16 warps/SM = 4/SMSP (the latency-hiding R8 lost at occ-1).
#define BM 256
#define BN 128
#define BK 64
#define KITERS (I_DIM / BK)      // 64
#define STAGES 3
#define NTHREADS 512

// SMEM stage: A[256][64]fp16 (32KB) | B[128][64]fp16 (16KB)
#define SA 0
#define SB 32768
#define STAGE_B 49152
#define SMEM_DYN (STAGES * STAGE_B)   // 147456 B (<= 227KB opt-in)
// 128-byte rows -> natural SW128 swizzle: chunk ^= (row & 7)

// ---------------------------------------------------------------------------
// Static scratch (allocation-free per harness rules)
// ---------------------------------------------------------------------------
__device__ __align__(256) __half g_x16[(size_t)M_DIM * I_DIM];   // 64 MB
__device__ __align__(256) __half g_w16[(size_t)O_DIM * I_DIM];   // 32 MB

// ---------------------------------------------------------------------------
// PTX helpers (sm_80-class: cp.async, ldmatrix, mma.sync)
// ---------------------------------------------------------------------------
__device__ __forceinline__ uint32_t smem_u32(const void* p) {
    uint32_t a;
    asm("{ .reg .u64 t; cvta.to.shared.u64 t, %1; cvt.u32.u64 %0, t; }"
        : "=r"(a) : "l"(p));
    return a;
}

#define CP_A16(dst, src) \
    asm volatile("cp.async.cg.shared.global [%0], [%1], 16;" \
                 :: "r"(dst), "l"(src) : "memory")
#define CP_COMMIT() asm volatile("cp.async.commit_group;" ::: "memory")
#define CP_WAIT1()  asm volatile("cp.async.wait_group 1;" ::: "memory")

__device__ __forceinline__ void ldsm4(uint32_t (&r)[4], uint32_t addr) {
    asm volatile("ldmatrix.sync.aligned.m8n8.x4.shared.b16 {%0,%1,%2,%3}, [%4];"
                 : "=r"(r[0]), "=r"(r[1]), "=r"(r[2]), "=r"(r[3]) : "r"(addr));
}

__device__ __forceinline__ void mma16816(float* d, const uint32_t* a, const uint32_t* b) {
    asm volatile(
        "mma.sync.aligned.m16n8k16.row.col.f32.f16.f16.f32 "
        "{%0,%1,%2,%3}, {%4,%5,%6,%7}, {%8,%9}, {%0,%1,%2,%3};"
        : "+f"(d[0]), "+f"(d[1]), "+f"(d[2]), "+f"(d[3])
        : "r"(a[0]), "r"(a[1]), "r"(a[2]), "r"(a[3]), "r"(b[0]), "r"(b[1]));
}

// ---------------------------------------------------------------------------
// Kernel 1: x -> fp16 (rel rounding ~2^-11; contributes ~1.3e-4 at output)
// ---------------------------------------------------------------------------
__global__ __launch_bounds__(256) void convert_x_kernel(const float* __restrict__ x) {
    const size_t i4 = ((size_t)blockIdx.x * 256 + threadIdx.x) * 4;
    const float4 v = *(const float4*)(x + i4);
    unsigned short h[4];
    h[0] = __half_as_ushort(__float2half_rn(v.x));
    h[1] = __half_as_ushort(__float2half_rn(v.y));
    h[2] = __half_as_ushort(__float2half_rn(v.z));
    h[3] = __half_as_ushort(__float2half_rn(v.w));
    uint2 hv;
    hv.x = (uint32_t)h[0] | ((uint32_t)h[1] << 16);
    hv.y = (uint32_t)h[2] | ((uint32_t)h[3] << 16);
    *(uint2*)(g_x16 + i4) = hv;
}

// ---------------------------------------------------------------------------
// Kernel 2: fused weight reconstruction -> fp16 (EXACT: |w_int| <= 255 needs
// 8 mantissa bits < fp16's 11; shift only moves the exponent).
// ---------------------------------------------------------------------------
__global__ __launch_bounds__(256) void weight_f16_kernel(
    const float* __restrict__ owr, const float* __restrict__ delta,
    const float* __restrict__ zp,  const float* __restrict__ aux,
    const float* __restrict__ loraA, const float* __restrict__ loraB)
{
    const int o  = blockIdx.y;
    const int i0 = (blockIdx.x * 256 + threadIdx.x) * 4;

    const float d  = delta[o];
    const float z  = zp[o];
    const float b0 = loraB[o * R_DIM + 0];
    const float b1 = loraB[o * R_DIM + 1];
    const float b2 = loraB[o * R_DIM + 2];
    const float b3 = loraB[o * R_DIM + 3];

    const size_t base = (size_t)o * I_DIM + i0;
    const float4 w4 = *(const float4*)(owr + base);
    const float4 x4 = *(const float4*)(aux + base);
    const float4 a0 = *(const float4*)(loraA + 0 * I_DIM + i0);
    const float4 a1 = *(const float4*)(loraA + 1 * I_DIM + i0);
    const float4 a2 = *(const float4*)(loraA + 2 * I_DIM + i0);
    const float4 a3 = *(const float4*)(loraA + 3 * I_DIM + i0);

    const float wv[4] = {w4.x, w4.y, w4.z, w4.w};
    const float av[4] = {x4.x, x4.y, x4.z, x4.w};
    const float A0[4] = {a0.x, a0.y, a0.z, a0.w};
    const float A1[4] = {a1.x, a1.y, a1.z, a1.w};
    const float A2[4] = {a2.x, a2.y, a2.z, a2.w};
    const float A3[4] = {a3.x, a3.y, a3.z, a3.w};

    unsigned short out[4];
#pragma unroll
    for (int j = 0; j < 4; j++) {
        const float w_int = wv[j] - z;
        const float denom = (w_int == 0.0f) ? 1.0f : w_int;
        float ba = b0 * A0[j];
        ba = fmaf(b1, A1[j], ba);
        ba = fmaf(b2, A2[j], ba);
        ba = fmaf(b3, A3[j], ba);
        const float wu = d + (av[j] + ba) / denom;
        const float s  = (wu > 0.0f) ? 1.0f : ((wu < 0.0f) ? -1.0f : 0.0f);
        const float shift = rintf(log2f(fabsf(wu) + 1e-16f));
        const float w = s * exp2f(shift) * w_int;   // exactly fp16-representable
        out[j] = __half_as_ushort(__float2half_rn(w));
    }
    uint2 pv;
    pv.x = (uint32_t)out[0] | ((uint32_t)out[1] << 16);
    pv.y = (uint32_t)out[2] | ((uint32_t)out[3] << 16);
    *(uint2*)(g_w16 + base) = pv;
}

// ---------------------------------------------------------------------------
// Kernel 3: mma.sync fp16 GEMM.  C = x16[M,K] * W16[N,K]^T + bias
//   256x128x64 CTA tile, 512 threads, 16 warps = 4(m) x 4(n), warp 64x32.
//   3-stage cp.async pipeline. W ([N,K], K-contig) IS col-major B for
//   mma.row.col. SW128 swizzle chunk ^= row&7 (conflict-free everywhere).
// ---------------------------------------------------------------------------
__global__ __launch_bounds__(NTHREADS, 1) void gemm_mma_kernel(
    const float* __restrict__ bias, float* __restrict__ C)
{
    extern __shared__ char smem[];
    const uint32_t sbase = smem_u32(smem);
    const int tid  = threadIdx.x;
    const int lane = tid & 31;
    const int wid  = tid >> 5;
    const int warp_m = wid >> 2;                 // 0..3 (64 rows each)
    const int warp_n = wid & 3;                  // 0..3 (32 cols each)
    const int bm = blockIdx.y * BM;
    const int bn = blockIdx.x * BN;

    // ---- loader: thread t -> row lr (0..63, +64 steps), 16B chunk lc (0..7)
    const int lr = tid >> 3;                     // 0..63
    const int lc = tid & 7;                      // chunk within 128B row
    const uint32_t so0 = (uint32_t)(lr * 128 + ((lc ^ (lr & 7)) * 16));
    const char* gA = (const char*)g_x16 + (size_t)(bm + lr) * (I_DIM * 2) + lc * 16;
    const char* gB = (const char*)g_w16 + (size_t)(bn + lr) * (I_DIM * 2) + lc * 16;
    const size_t RSTEP = (size_t)64 * (I_DIM * 2);   // 64 rows

    auto load_stage = [&](int s, int kt) {
        const uint32_t st = sbase + s * STAGE_B;
        const size_t ko = (size_t)kt * (BK * 2);
#pragma unroll
        for (int it = 0; it < 4; ++it)            // A: 256 rows
            CP_A16(st + SA + so0 + it * 8192, gA + ko + it * RSTEP);
#pragma unroll
        for (int it = 0; it < 2; ++it)            // B: 128 rows
            CP_A16(st + SB + so0 + it * 8192, gB + ko + it * RSTEP);
    };

    // ---- ldmatrix lane offsets for ks=0; addr ^ (ks*32) selects k16 step
    // (chunk = (ks<<1)|bit, disjoint bits -> XOR distributes through swizzle)
    uint32_t aoff[4], boff[2];
    {
        const int ar  = warp_m * 64 + (lane & 15);
        const int ach = lane >> 4;                       // k-chunk low bit
#pragma unroll
        for (int i = 0; i < 4; ++i) {
            const int r = ar + i * 16;
            aoff[i] = (uint32_t)(r * 128 + ((ach ^ (r & 7)) * 16));
        }
        const int br  = warp_n * 32 + ((lane >> 4) << 3) + (lane & 7);
        const int bch = (lane >> 3) & 1;
#pragma unroll
        for (int j = 0; j < 2; ++j) {
            const int r = br + j * 16;
            boff[j] = (uint32_t)(r * 128 + ((bch ^ (r & 7)) * 16));
        }
    }

    float acc[4][4][4];
#pragma unroll
    for (int i = 0; i < 4; ++i)
#pragma unroll
        for (int j = 0; j < 4; ++j)
#pragma unroll
            for (int c = 0; c < 4; ++c) acc[i][j][c] = 0.0f;

    // ---- prologue: fill 2 stages ----
    load_stage(0, 0); CP_COMMIT();
    load_stage(1, 1); CP_COMMIT();

    for (int kt = 0; kt < KITERS; ++kt) {
        CP_WAIT1();                  // stage kt resident (groups retire in order)
        __syncthreads();             // all warps done reading stage (kt-1)%3
        if (kt + 2 < KITERS) load_stage((kt + 2) % STAGES, kt + 2);
        CP_COMMIT();                 // empty tail groups keep wait index uniform

        const uint32_t st = sbase + (kt % STAGES) * STAGE_B;
#pragma unroll
        for (int ks = 0; ks < 4; ++ks) {
            const uint32_t kx = ks * 32;         // 2 chunks of 16B per k16 step
            uint32_t af[4][4], bf[2][4];
#pragma unroll
            for (int i = 0; i < 4; ++i)
                ldsm4(af[i], st + SA + (aoff[i] ^ kx));
#pragma unroll
            for (int j = 0; j < 2; ++j)
                ldsm4(bf[j], st + SB + (boff[j] ^ kx));
            // bf[j] = { b(n=16j+0..7,k0-7), b(..,k8-15), b(n+8,k0-7), b(n+8,k8-15) }
#pragma unroll
            for (int i = 0; i < 4; ++i)
#pragma unroll
                for (int j = 0; j < 2; ++j) {
                    mma16816(acc[i][2 * j],     af[i], &bf[j][0]);
                    mma16816(acc[i][2 * j + 1], af[i], &bf[j][2]);
                }
        }
    }

    // ---- epilogue: d-frag rows lane>>2 (+8), cols (lane&3)*2 ----
#pragma unroll
    for (int i = 0; i < 4; ++i) {
        const int r0 = bm + warp_m * 64 + i * 16 + (lane >> 2);
#pragma unroll
        for (int jn = 0; jn < 4; ++jn) {
            const int col = bn + warp_n * 32 + jn * 8 + (lane & 3) * 2;
            const float2 bz = *(const float2*)(bias + col);
            float2 v0 = make_float2(acc[i][jn][0] + bz.x, acc[i][jn][1] + bz.y);
            float2 v1 = make_float2(acc[i][jn][2] + bz.x, acc[i][jn][3] + bz.y);
            *(float2*)(C + (size_t)r0 * O_DIM + col)       = v0;
            *(float2*)(C + (size_t)(r0 + 8) * O_DIM + col) = v1;
        }
    }
}

// ---------------------------------------------------------------------------
// Launch
// ---------------------------------------------------------------------------
extern "C" void kernel_launch(void* const* d_in, const int* in_sizes, int n_in,
                              void* d_out, int out_size)
{
    const float* x     = (const float*)d_in[0];
    const float* owr   = (const float*)d_in[1];
    const float* delta = (const float*)d_in[2];
    const float* zp    = (const float*)d_in[3];
    const float* aux   = (const float*)d_in[4];
    const float* loraA = (const float*)d_in[5];
    const float* loraB = (const float*)d_in[6];
    const float* bias  = (const float*)d_in[7];
    float* out = (float*)d_out;

    cudaFuncSetAttribute(gemm_mma_kernel,
                         cudaFuncAttributeMaxDynamicSharedMemorySize, SMEM_DYN);

    // 1) x -> fp16
    convert_x_kernel<<<(int)(((size_t)M_DIM * I_DIM) / (256 * 4)), 256>>>(x);

    // 2) weight reconstruction -> fp16 (exact representation)
    weight_f16_kernel<<<dim3(I_DIM / 1024, O_DIM), 256>>>(owr, delta, zp, aux, loraA, loraB);

    // 3) tensor-core GEMM (fp16 mma.sync, fp32 accum) + bias
    gemm_mma_kernel<<<dim3(O_DIM / BN, M_DIM / BM), NTHREADS, SMEM_DYN>>>(bias, out);
}

// round 11
// speedup vs baseline: 1.2093x; 1.2093x over previous
#include <cuda_runtime.h>
#include <cuda_fp16.h>
#include <cstdint>

// ---------------------------------------------------------------------------
// Problem dims
// ---------------------------------------------------------------------------
#define I_DIM 4096   // K
#define O_DIM 4096   // N
#define M_DIM 8192   // B*S
#define R_DIM 4

// GEMM tiling: 128x128x64 CTA tile, 8 warps = 4(m) x 2(n), warp tile 32x64,
// 3-stage cp.async pipeline, 2 independent CTAs/SM (the R6/R9-proven point).
#define BM 128
#define BN 128
#define BK 64
#define KITERS (I_DIM / BK)      // 64
#define STAGES 3

// SMEM stage layout: A[128][64]fp16 (16KB) | B[128][64]fp16 (16KB)
#define SA 0
#define SB 16384
#define STAGE_B 32768
#define SMEM_DYN (STAGES * STAGE_B)   // 98304 B -> 2 CTAs/SM (192KB <= 227KB)
// 128-byte rows -> natural SW128 swizzle: chunk ^= (row & 7)

// ---------------------------------------------------------------------------
// Static scratch (allocation-free per harness rules)
// ---------------------------------------------------------------------------
__device__ __align__(256) __half g_x16[(size_t)M_DIM * I_DIM];   // 64 MB
__device__ __align__(256) __half g_w16[(size_t)O_DIM * I_DIM];   // 32 MB

// ---------------------------------------------------------------------------
// PTX helpers (sm_80-class: cp.async, ldmatrix, mma.sync)
// ---------------------------------------------------------------------------
__device__ __forceinline__ uint32_t smem_u32(const void* p) {
    uint32_t a;
    asm("{ .reg .u64 t; cvta.to.shared.u64 t, %1; cvt.u32.u64 %0, t; }"
        : "=r"(a) : "l"(p));
    return a;
}

#define CP_A16(dst, src) \
    asm volatile("cp.async.cg.shared.global [%0], [%1], 16;" \
                 :: "r"(dst), "l"(src) : "memory")
#define CP_COMMIT() asm volatile("cp.async.commit_group;" ::: "memory")
#define CP_WAIT1()  asm volatile("cp.async.wait_group 1;" ::: "memory")

__device__ __forceinline__ void ldsm4(uint32_t (&r)[4], uint32_t addr) {
    asm volatile("ldmatrix.sync.aligned.m8n8.x4.shared.b16 {%0,%1,%2,%3}, [%4];"
                 : "=r"(r[0]), "=r"(r[1]), "=r"(r[2]), "=r"(r[3]) : "r"(addr));
}

__device__ __forceinline__ void mma16816(float* d, const uint32_t* a, const uint32_t* b) {
    asm volatile(
        "mma.sync.aligned.m16n8k16.row.col.f32.f16.f16.f32 "
        "{%0,%1,%2,%3}, {%4,%5,%6,%7}, {%8,%9}, {%0,%1,%2,%3};"
        : "+f"(d[0]), "+f"(d[1]), "+f"(d[2]), "+f"(d[3])
        : "r"(a[0]), "r"(a[1]), "r"(a[2]), "r"(a[3]), "r"(b[0]), "r"(b[1]));
}

// streaming (evict-first) store: keeps C writes from thrashing x16/w16 out of L2
__device__ __forceinline__ void stg_cs_f2(float* p, float2 v) {
    asm volatile("st.global.cs.v2.f32 [%0], {%1, %2};"
                 :: "l"(p), "f"(v.x), "f"(v.y) : "memory");
}

// ---------------------------------------------------------------------------
// Kernel 1: x -> fp16 (rel rounding ~2^-11; contributes ~1.3e-4 at output)
// ---------------------------------------------------------------------------
__global__ __launch_bounds__(256) void convert_x_kernel(const float* __restrict__ x) {
    const size_t i4 = ((size_t)blockIdx.x * 256 + threadIdx.x) * 4;
    const float4 v = *(const float4*)(x + i4);
    unsigned short h[4];
    h[0] = __half_as_ushort(__float2half_rn(v.x));
    h[1] = __half_as_ushort(__float2half_rn(v.y));
    h[2] = __half_as_ushort(__float2half_rn(v.z));
    h[3] = __half_as_ushort(__float2half_rn(v.w));
    uint2 hv;
    hv.x = (uint32_t)h[0] | ((uint32_t)h[1] << 16);
    hv.y = (uint32_t)h[2] | ((uint32_t)h[3] << 16);
    *(uint2*)(g_x16 + i4) = hv;
}

// ---------------------------------------------------------------------------
// Kernel 2: fused weight reconstruction -> fp16 (EXACT: |w_int| <= 255 needs
// 8 mantissa bits < fp16's 11; shift only moves the exponent).
// ---------------------------------------------------------------------------
__global__ __launch_bounds__(256) void weight_f16_kernel(
    const float* __restrict__ owr, const float* __restrict__ delta,
    const float* __restrict__ zp,  const float* __restrict__ aux,
    const float* __restrict__ loraA, const float* __restrict__ loraB)
{
    const int o  = blockIdx.y;
    const int i0 = (blockIdx.x * 256 + threadIdx.x) * 4;

    const float d  = delta[o];
    const float z  = zp[o];
    const float b0 = loraB[o * R_DIM + 0];
    const float b1 = loraB[o * R_DIM + 1];
    const float b2 = loraB[o * R_DIM + 2];
    const float b3 = loraB[o * R_DIM + 3];

    const size_t base = (size_t)o * I_DIM + i0;
    const float4 w4 = *(const float4*)(owr + base);
    const float4 x4 = *(const float4*)(aux + base);
    const float4 a0 = *(const float4*)(loraA + 0 * I_DIM + i0);
    const float4 a1 = *(const float4*)(loraA + 1 * I_DIM + i0);
    const float4 a2 = *(const float4*)(loraA + 2 * I_DIM + i0);
    const float4 a3 = *(const float4*)(loraA + 3 * I_DIM + i0);

    const float wv[4] = {w4.x, w4.y, w4.z, w4.w};
    const float av[4] = {x4.x, x4.y, x4.z, x4.w};
    const float A0[4] = {a0.x, a0.y, a0.z, a0.w};
    const float A1[4] = {a1.x, a1.y, a1.z, a1.w};
    const float A2[4] = {a2.x, a2.y, a2.z, a2.w};
    const float A3[4] = {a3.x, a3.y, a3.z, a3.w};

    unsigned short out[4];
#pragma unroll
    for (int j = 0; j < 4; j++) {
        const float w_int = wv[j] - z;
        const float denom = (w_int == 0.0f) ? 1.0f : w_int;
        float ba = b0 * A0[j];
        ba = fmaf(b1, A1[j], ba);
        ba = fmaf(b2, A2[j], ba);
        ba = fmaf(b3, A3[j], ba);
        const float wu = d + (av[j] + ba) / denom;
        const float s  = (wu > 0.0f) ? 1.0f : ((wu < 0.0f) ? -1.0f : 0.0f);
        const float shift = rintf(log2f(fabsf(wu) + 1e-16f));
        const float w = s * exp2f(shift) * w_int;   // exactly fp16-representable
        out[j] = __half_as_ushort(__float2half_rn(w));
    }
    uint2 pv;
    pv.x = (uint32_t)out[0] | ((uint32_t)out[1] << 16);
    pv.y = (uint32_t)out[2] | ((uint32_t)out[3] << 16);
    *(uint2*)(g_w16 + base) = pv;
}

// ---------------------------------------------------------------------------
// Kernel 3: mma.sync fp16 GEMM.  C = x16[M,K] * W16[N,K]^T + bias
//   Identical compute structure to the 758us R9 kernel, plus:
//   - st.global.cs epilogue (C never pollutes L2's x/w residency)
//   - kt loop unrolled x3 so stage offsets are compile-time constants
// ---------------------------------------------------------------------------
__global__ __launch_bounds__(256, 2) void gemm_mma_kernel(
    const float* __restrict__ bias, float* __restrict__ C)
{
    extern __shared__ char smem[];
    const uint32_t sbase = smem_u32(smem);
    const int tid  = threadIdx.x;
    const int lane = tid & 31;
    const int wid  = tid >> 5;
    const int warp_m = wid >> 1;                 // 0..3 (32 rows each)
    const int warp_n = wid & 1;                  // 0..1 (64 cols each)
    const int bm = blockIdx.y * BM;
    const int bn = blockIdx.x * BN;

    // ---- loader: thread t -> row lr (0..31, +32 steps), 16B chunk lc (0..7)
    const int lr = tid >> 3;
    const int lc = tid & 7;
    const uint32_t so0 = (uint32_t)(lr * 128 + ((lc ^ (lr & 7)) * 16));
    const char* gA = (const char*)g_x16 + (size_t)(bm + lr) * (I_DIM * 2) + lc * 16;
    const char* gB = (const char*)g_w16 + (size_t)(bn + lr) * (I_DIM * 2) + lc * 16;
    const size_t RSTEP = (size_t)32 * (I_DIM * 2);

    auto load_stage = [&](uint32_t st, int kt) {
        const size_t ko = (size_t)kt * (BK * 2);
#pragma unroll
        for (int it = 0; it < 4; ++it) {          // 128 rows per operand
            CP_A16(st + SA + so0 + it * 4096, gA + ko + it * RSTEP);
            CP_A16(st + SB + so0 + it * 4096, gB + ko + it * RSTEP);
        }
    };

    // ---- ldmatrix lane offsets for ks=0; addr ^ (ks*32) selects k16 step ----
    uint32_t aoff[2], boff[4];
    {
        const int ar  = warp_m * 32 + (lane & 15);
        const int ach = lane >> 4;
#pragma unroll
        for (int i = 0; i < 2; ++i) {
            const int r = ar + i * 16;
            aoff[i] = (uint32_t)(r * 128 + ((ach ^ (r & 7)) * 16));
        }
        const int br  = warp_n * 64 + ((lane >> 4) << 3) + (lane & 7);
        const int bch = (lane >> 3) & 1;
#pragma unroll
        for (int j = 0; j < 4; ++j) {
            const int r = br + j * 16;
            boff[j] = (uint32_t)(r * 128 + ((bch ^ (r & 7)) * 16));
        }
    }

    float acc[2][8][4];
#pragma unroll
    for (int i = 0; i < 2; ++i)
#pragma unroll
        for (int j = 0; j < 8; ++j)
#pragma unroll
            for (int c = 0; c < 4; ++c) acc[i][j][c] = 0.0f;

    // per-kt body with compile-time stage offsets
    auto body = [&](int kt, uint32_t st_cur, uint32_t st_next) {
        CP_WAIT1();                  // stage kt resident
        __syncthreads();             // stage being overwritten is fully read
        if (kt + 2 < KITERS) load_stage(st_next, kt + 2);
        CP_COMMIT();
#pragma unroll
        for (int ks = 0; ks < 4; ++ks) {
            const uint32_t kx = ks * 32;
            uint32_t af[2][4], bf[4][4];
#pragma unroll
            for (int i = 0; i < 2; ++i)
                ldsm4(af[i], st_cur + SA + (aoff[i] ^ kx));
#pragma unroll
            for (int j = 0; j < 4; ++j)
                ldsm4(bf[j], st_cur + SB + (boff[j] ^ kx));
#pragma unroll
            for (int i = 0; i < 2; ++i)
#pragma unroll
                for (int j = 0; j < 4; ++j) {
                    mma16816(acc[i][2 * j],     af[i], &bf[j][0]);
                    mma16816(acc[i][2 * j + 1], af[i], &bf[j][2]);
                }
        }
    };

    const uint32_t s0 = sbase, s1 = sbase + STAGE_B, s2 = sbase + 2 * STAGE_B;

    // ---- prologue: fill 2 stages ----
    load_stage(s0, 0); CP_COMMIT();
    load_stage(s1, 1); CP_COMMIT();

    // KITERS = 64 = 21*3 + 1: unrolled groups of 3, then the final kt (stage 0)
#pragma unroll 1
    for (int kt = 0; kt < 63; kt += 3) {
        body(kt + 0, s0, s2);
        body(kt + 1, s1, s0);
        body(kt + 2, s2, s1);
    }
    body(63, s0, s2);

    // ---- epilogue: streaming stores (evict-first; protect L2 residency) ----
#pragma unroll
    for (int i = 0; i < 2; ++i) {
        const int r0 = bm + warp_m * 32 + i * 16 + (lane >> 2);
#pragma unroll
        for (int jn = 0; jn < 8; ++jn) {
            const int col = bn + warp_n * 64 + jn * 8 + (lane & 3) * 2;
            const float2 bz = *(const float2*)(bias + col);
            stg_cs_f2(C + (size_t)r0 * O_DIM + col,
                      make_float2(acc[i][jn][0] + bz.x, acc[i][jn][1] + bz.y));
            stg_cs_f2(C + (size_t)(r0 + 8) * O_DIM + col,
                      make_float2(acc[i][jn][2] + bz.x, acc[i][jn][3] + bz.y));
        }
    }
}

// ---------------------------------------------------------------------------
// Launch
// ---------------------------------------------------------------------------
extern "C" void kernel_launch(void* const* d_in, const int* in_sizes, int n_in,
                              void* d_out, int out_size)
{
    const float* x     = (const float*)d_in[0];
    const float* owr   = (const float*)d_in[1];
    const float* delta = (const float*)d_in[2];
    const float* zp    = (const float*)d_in[3];
    const float* aux   = (const float*)d_in[4];
    const float* loraA = (const float*)d_in[5];
    const float* loraB = (const float*)d_in[6];
    const float* bias  = (const float*)d_in[7];
    float* out = (float*)d_out;

    cudaFuncSetAttribute(gemm_mma_kernel,
                         cudaFuncAttributeMaxDynamicSharedMemorySize, SMEM_DYN);

    // 1) x -> fp16
    convert_x_kernel<<<(int)(((size_t)M_DIM * I_DIM) / (256 * 4)), 256>>>(x);

    // 2) weight reconstruction -> fp16 (exact representation)
    weight_f16_kernel<<<dim3(I_DIM / 1024, O_DIM), 256>>>(owr, delta, zp, aux, loraA, loraB);

    // 3) tensor-core GEMM (fp16 mma.sync, fp32 accum) + bias
    gemm_mma_kernel<<<dim3(O_DIM / BN, M_DIM / BM), 256, SMEM_DYN>>>(bias, out);
}